// round 16
// baseline (speedup 1.0000x reference)
#include <cuda_runtime.h>
#include <cuda_fp16.h>
#include <cstdint>

// Problem constants
#define B_   4
#define T_   32
#define D_   768
#define P_   256
#define BS_  1024
#define M_   32768
#define NH_  12
#define HD_  64
#define NQKV 2304          // fused Q|K|V output width

// hh / QKV rows: m = bs*T + t   (attention-friendly)
// aout rows:     m = t*BS + bs  (oproj fused-transpose-friendly)

// GEMM tiling: 128x128, BK=64, 4 warps (2m x 2n), warp tile 64x64, 2 CTAs/SM
#define BM   128
#define BN   128
#define BK   64
#define NKT  (D_ / BK)     // 12
#define STG_BYTES 32768    // A 16K + B 16K
#define B_OFFS 16384

#define SW128(b) ((b) ^ (((b) >> 3) & 0x70))

// Attention smem layout (per warp): Q 32x72h, K 32x72h, Vt 64x40h
#define QK_STRIDE_B 144
#define VT_STRIDE_B 80
#define AQ_OFF 0
#define AK_OFF 4608
#define AVT_OFF 9216
#define AWARP_BYTES 14336
#define AUPEN_OFF (4 * AWARP_BYTES)
#define ATTN_SMEM (AUPEN_OFF + 128)

// ---------------- scratch (device globals; no cudaMalloc allowed) ----------
__device__ __half g_hh  [(size_t)M_ * D_];       // h_seq fp16, [bs][t][d]
__device__ __half g_aout[(size_t)M_ * D_];       // attention out fp16, [t][bs][d]
__device__ __half g_wqkv[(size_t)NQKV * D_];     // fused Wq|Wk|Wv fp16
__device__ __half g_wo  [(size_t)D_ * D_];
__device__ float  g_bqkv[NQKV];
__device__ __half g_QKV [(size_t)M_ * NQKV];     // fused Q|K|V fp16, [bs][t]
__device__ float  g_upen[M_];                    // [bs][t]

// ---------------- PTX helpers (base-PTX, sm_80-era) ------------------------
__device__ __forceinline__ uint32_t smem_u32(const void* p) {
    uint32_t a;
    asm("{ .reg .u64 t; cvta.to.shared.u64 t, %1; cvt.u32.u64 %0, t; }"
        : "=r"(a) : "l"(p));
    return a;
}

__device__ __forceinline__ void cp16(uint32_t dst, const void* src) {
    asm volatile("cp.async.cg.shared.global [%0], [%1], 16;" :: "r"(dst), "l"(src));
}
#define CP_COMMIT() asm volatile("cp.async.commit_group;" ::: "memory")
#define CP_WAIT(n)  asm volatile("cp.async.wait_group %0;" :: "n"(n) : "memory")

__device__ __forceinline__ void ldsm4(uint32_t (&r)[4], uint32_t addr) {
    asm volatile("ldmatrix.sync.aligned.m8n8.x4.shared.b16 {%0,%1,%2,%3}, [%4];"
                 : "=r"(r[0]), "=r"(r[1]), "=r"(r[2]), "=r"(r[3]) : "r"(addr));
}

__device__ __forceinline__ void mma16816(float (&d)[4], const uint32_t (&a)[4],
                                         uint32_t b0, uint32_t b1) {
    asm volatile(
        "mma.sync.aligned.m16n8k16.row.col.f32.f16.f16.f32 "
        "{%0,%1,%2,%3}, {%4,%5,%6,%7}, {%8,%9}, {%0,%1,%2,%3};"
        : "+f"(d[0]), "+f"(d[1]), "+f"(d[2]), "+f"(d[3])
        : "r"(a[0]), "r"(a[1]), "r"(a[2]), "r"(a[3]), "r"(b0), "r"(b1));
}

__device__ __forceinline__ uint32_t packh2(float x, float y) {
    __half2 h = __floats2half2_rn(x, y);
    return *reinterpret_cast<uint32_t*>(&h);
}

__device__ __forceinline__ void store2(float* p, float x, float y) {
    *reinterpret_cast<float2*>(p) = make_float2(x, y);
}
__device__ __forceinline__ void store2(__half* p, float x, float y) {
    *reinterpret_cast<__half2*>(p) = __floats2half2_rn(x, y);
}

// ---------------------------------------------------------------------------
// transpose to [bs][t][d] + fp16 convert; 64d x 32p tiles, __half2 stores
// ---------------------------------------------------------------------------
__global__ __launch_bounds__(1024) void transpose_in_h(const float* __restrict__ src,
                                                       __half* __restrict__ dst) {
    __shared__ float tile[64][33];
    int bt = blockIdx.z, b = bt >> 5, t = bt & 31;
    int dblk = blockIdx.y * 64, pblk = blockIdx.x * 32;
    int tx = threadIdx.x, ty = threadIdx.y;

    const float* sp = src + ((size_t)bt * D_ + dblk + ty) * P_ + pblk + tx;
    tile[ty][tx]      = sp[0];
    tile[ty + 32][tx] = sp[(size_t)32 * P_];
    __syncthreads();
    int d2 = 2 * tx;
    int p2 = pblk + ty;
    __half2 v = __floats2half2_rn(tile[d2][ty], tile[d2 + 1][ty]);
    *reinterpret_cast<__half2*>(
        dst + ((size_t)(b * P_ + p2) * T_ + t) * D_ + dblk + d2) = v;
}

// ---------------------------------------------------------------------------
// weight convert (all 4) + bias pack fold
// ---------------------------------------------------------------------------
__global__ __launch_bounds__(256) void wconv4(const float* __restrict__ Wq,
                                              const float* __restrict__ Wk,
                                              const float* __restrict__ Wv,
                                              const float* __restrict__ Wo,
                                              __half* __restrict__ wqkv,
                                              __half* __restrict__ wo,
                                              const float* __restrict__ bq,
                                              const float* __restrict__ bk,
                                              const float* __restrict__ bv,
                                              float* __restrict__ bqkv) {
    int idx = blockIdx.x * 256 + threadIdx.x;
    int w = blockIdx.y;
    const float* src = (w == 0) ? Wq : (w == 1) ? Wk : (w == 2) ? Wv : Wo;
    __half* dst = (w == 3) ? wo : wqkv + (size_t)w * D_ * D_;
    float4 v = *reinterpret_cast<const float4*>(src + idx * 4);
    __half2 h0 = __floats2half2_rn(v.x, v.y);
    __half2 h1 = __floats2half2_rn(v.z, v.w);
    uint2 o = make_uint2(*reinterpret_cast<uint32_t*>(&h0),
                         *reinterpret_cast<uint32_t*>(&h1));
    *reinterpret_cast<uint2*>(dst + idx * 4) = o;

    if (w == 3 && idx < NQKV) {
        float bv_ = (idx < D_) ? bq[idx]
                  : (idx < 2 * D_) ? bk[idx - D_] : bv[idx - 2 * D_];
        bqkv[idx] = bv_;
    }
}

// ---------------------------------------------------------------------------
// u_pen   [bs][t]
// ---------------------------------------------------------------------------
__global__ __launch_bounds__(256) void upen_kernel(const float* __restrict__ u,
                                                   const float* __restrict__ lam,
                                                   float* __restrict__ upen) {
    int bt = blockIdx.x, b = bt >> 5, t = bt & 31;
    int p = threadIdx.x;
    const float* up = u + (size_t)bt * D_ * P_ + p;
    float acc = 0.f;
#pragma unroll 8
    for (int d = 0; d < D_; d++) acc += up[(size_t)d * P_];
    upen[(b * P_ + p) * T_ + t] = lam[(size_t)bt * P_ + p] * acc * (1.0f / (float)D_);
}

// ---------------------------------------------------------------------------
// GEMM core shared by both kernels: 128x128x768, 4 warps x (64x64)
// Each warp: afr[4] (m-tiles), bfr[4] (n-pairs), 32 MMA per k16 step.
// ---------------------------------------------------------------------------
struct GemmAcc { float a[4][8][4]; };

template <typename EpiF>
__device__ __forceinline__ void gemm_core(const __half* __restrict__ A,
                                          const __half* __restrict__ Wt,
                                          char* dyn, int mblk, int nblk,
                                          EpiF epi) {
    const uint32_t dynb = smem_u32(dyn);
    const int tid  = threadIdx.x;
    const int wid  = tid >> 5;
    const int lane = tid & 31;

    const int warp_m = (wid >> 1) * 64;   // 0,64
    const int warp_n = (wid & 1) * 64;    // 0,64

    const __half* Ab = A  + (size_t)mblk * D_;
    const __half* Bb = Wt + (size_t)nblk * D_;

    // 2048 chunks / 128 threads = 16 per thread
    auto load_tile = [&](int stage, int kt) {
        uint32_t sb = dynb + stage * STG_BYTES;
        const __half* Ak = Ab + kt * BK;
        const __half* Bk = Bb + kt * BK;
#pragma unroll
        for (int i = 0; i < 16; ++i) {
            int c = tid + 128 * i;
            if (c < 1024) {
                int r = c >> 3, kc = c & 7;
                cp16(sb + SW128(r * 128 + kc * 16),
                     Ak + (size_t)r * D_ + kc * 8);
            } else {
                int c2 = c - 1024;
                int r = c2 >> 3, kc = c2 & 7;
                cp16(sb + B_OFFS + SW128(r * 128 + kc * 16),
                     Bk + (size_t)r * D_ + kc * 8);
            }
        }
        CP_COMMIT();
    };

    const int a_row = warp_m + (lane & 15);
    const int a_kh  = lane >> 4;
    const int b_row = warp_n + (lane & 7) + ((lane >> 4) << 3);
    const int b_kh  = (lane >> 3) & 1;

    GemmAcc acc;
#pragma unroll
    for (int mi = 0; mi < 4; mi++)
#pragma unroll
        for (int ni = 0; ni < 8; ni++)
#pragma unroll
            for (int e = 0; e < 4; e++) acc.a[mi][ni][e] = 0.f;

    load_tile(0, 0);
    load_tile(1, 1);

    for (int kt = 0; kt < NKT; ++kt) {
        const int cur = kt % 3;
        if (kt < NKT - 1) CP_WAIT(1); else CP_WAIT(0);
        __syncthreads();
        if (kt + 2 < NKT) load_tile((kt + 2) % 3, kt + 2);

        const uint32_t sb = dynb + cur * STG_BYTES;
#pragma unroll
        for (int s = 0; s < 4; ++s) {
            uint32_t bfr[4][4];
#pragma unroll
            for (int nj = 0; nj < 4; nj++)
                ldsm4(bfr[nj], sb + B_OFFS +
                      SW128((b_row + nj * 16) * 128 + (s * 2 + b_kh) * 16));
            uint32_t afr[4][4];
#pragma unroll
            for (int mi = 0; mi < 4; mi++)
                ldsm4(afr[mi], sb +
                      SW128((a_row + mi * 16) * 128 + (s * 2 + a_kh) * 16));
#pragma unroll
            for (int mi = 0; mi < 4; mi++) {
#pragma unroll
                for (int ni = 0; ni < 8; ni++) {
                    uint32_t b0 = bfr[ni >> 1][(ni & 1) * 2 + 0];
                    uint32_t b1 = bfr[ni >> 1][(ni & 1) * 2 + 1];
                    mma16816(acc.a[mi][ni], afr[mi], b0, b1);
                }
            }
        }
    }
    epi(acc, warp_m, warp_n, lane);
}

// ---------------------------------------------------------------------------
// HMMA GEMM (QKV): C fp16 stride NQKV, smem-staged coalesced epilogue
// ---------------------------------------------------------------------------
__global__ __launch_bounds__(128, 2) void gemm_qkv(const __half* __restrict__ A,
                                                   const __half* __restrict__ Wt,
                                                   const float* __restrict__ bias,
                                                   __half* __restrict__ C) {
    extern __shared__ __align__(128) char dyn[];
    const int mblk = blockIdx.y * BM;
    const int nblk = blockIdx.x * BN;
    const int tid  = threadIdx.x;
    const int wid  = tid >> 5;

    gemm_core(A, Wt, dyn, mblk, nblk,
        [&](GemmAcc& acc, int warp_m, int warp_n, int lane) {
            const int rloc0 = warp_m + (lane >> 2);
            const int cloc0 = warp_n + (lane & 3) * 2;
            float2 bb[8];
#pragma unroll
            for (int ni = 0; ni < 8; ni++) {
                int n = nblk + cloc0 + ni * 8;
                bb[ni].x = __ldg(&bias[n]);
                bb[ni].y = __ldg(&bias[n + 1]);
            }
            __syncthreads();
            __half* cst = reinterpret_cast<__half*>(dyn);
#pragma unroll
            for (int mi = 0; mi < 4; mi++) {
                int r0 = rloc0 + mi * 16;
#pragma unroll
                for (int ni = 0; ni < 8; ni++) {
                    int n = cloc0 + ni * 8;
                    store2(cst + (size_t)r0 * 136 + n,
                           acc.a[mi][ni][0] + bb[ni].x, acc.a[mi][ni][1] + bb[ni].y);
                    store2(cst + (size_t)(r0 + 8) * 136 + n,
                           acc.a[mi][ni][2] + bb[ni].x, acc.a[mi][ni][3] + bb[ni].y);
                }
            }
            __syncthreads();
#pragma unroll
            for (int i = 0; i < 32; ++i) {
                int r = wid * 32 + i;
                uint2 v = *reinterpret_cast<uint2*>(cst + (size_t)r * 136 + lane * 4);
                *reinterpret_cast<uint2*>(C + (size_t)(mblk + r) * NQKV + nblk + lane * 4) = v;
            }
        });
}

// ---------------------------------------------------------------------------
// HMMA GEMM (O proj) with FUSED TRANSPOSE epilogue:
// A = aout [t][bs][d]; writes final out (B,T,D,P) fp32 directly.
// ---------------------------------------------------------------------------
__global__ __launch_bounds__(128, 2) void gemm_oproj(const __half* __restrict__ A,
                                                     const __half* __restrict__ Wt,
                                                     const float* __restrict__ bias,
                                                     float* __restrict__ out) {
    extern __shared__ __align__(128) char dyn[];
    const int mblk = blockIdx.y * BM;
    const int nblk = blockIdx.x * BN;
    const int tid  = threadIdx.x;

    gemm_core(A, Wt, dyn, mblk, nblk,
        [&](GemmAcc& acc, int warp_m, int warp_n, int lane) {
            float* stage = reinterpret_cast<float*>(dyn);
            const int rloc0 = warp_m + (lane >> 2);
            const int nloc0 = warp_n + (lane & 3) * 2;
            float2 bb[8];
#pragma unroll
            for (int ni = 0; ni < 8; ni++) {
                int n = nblk + nloc0 + ni * 8;
                bb[ni].x = __ldg(&bias[n]);
                bb[ni].y = __ldg(&bias[n + 1]);
            }
            __syncthreads();
#pragma unroll
            for (int mi = 0; mi < 4; mi++) {
                int r0 = rloc0 + mi * 16;
#pragma unroll
                for (int ni = 0; ni < 8; ni++) {
                    int n = nloc0 + ni * 8;
                    stage[(size_t)r0 * 129 + n]           = acc.a[mi][ni][0] + bb[ni].x;
                    stage[(size_t)r0 * 129 + n + 1]       = acc.a[mi][ni][1] + bb[ni].y;
                    stage[(size_t)(r0 + 8) * 129 + n]     = acc.a[mi][ni][2] + bb[ni].x;
                    stage[(size_t)(r0 + 8) * 129 + n + 1] = acc.a[mi][ni][3] + bb[ni].y;
                }
            }
            __syncthreads();

            const int t  = mblk >> 10;
            const int b  = (mblk & 1023) >> 8;
            const int p0 = mblk & 255;
            float* obase = out + ((size_t)(b * T_ + t) * D_ + nblk) * P_ + p0;
#pragma unroll
            for (int i = 0; i < 32; ++i) {
                int c = tid + 128 * i;
                int dn = c >> 5, f4 = c & 31;
                float4 v;
                v.x = stage[(size_t)(f4 * 4 + 0) * 129 + dn];
                v.y = stage[(size_t)(f4 * 4 + 1) * 129 + dn];
                v.z = stage[(size_t)(f4 * 4 + 2) * 129 + dn];
                v.w = stage[(size_t)(f4 * 4 + 3) * 129 + dn];
                *reinterpret_cast<float4*>(obase + (size_t)dn * P_ + f4 * 4) = v;
            }
        });
}

// ---------------------------------------------------------------------------
// HMMA attention: 1 warp per (bs, head). QKV [bs][t] contiguous loads;
// writes aout [t][bs] via smem-staged coalesced row stores.
// ---------------------------------------------------------------------------
__global__ __launch_bounds__(128) void attn_mma(const __half* __restrict__ QKV,
                                                const float* __restrict__ upen,
                                                __half* __restrict__ O) {
    extern __shared__ __align__(128) char asm_[];
    const int bs   = blockIdx.x;
    const int wid  = threadIdx.x >> 5;
    const int lane = threadIdx.x & 31;
    const int head = blockIdx.y * 4 + wid;

    char* wb = asm_ + wid * AWARP_BYTES;
    const uint32_t wbase = smem_u32(asm_) + wid * AWARP_BYTES;
    float* us = reinterpret_cast<float*>(asm_ + AUPEN_OFF);

    if (threadIdx.x < 32) us[threadIdx.x] = upen[bs * T_ + threadIdx.x];

    const __half* hb = QKV + (size_t)(bs * T_) * NQKV + head * HD_;
#pragma unroll
    for (int i = 0; i < 8; ++i) {
        int id = lane + 32 * i;
        int r = id >> 3, c = id & 7;
        const __half* qsrc = hb + (size_t)r * NQKV + c * 8;
        *reinterpret_cast<uint4*>(wb + AQ_OFF + r * QK_STRIDE_B + c * 16) =
            *reinterpret_cast<const uint4*>(qsrc);
        *reinterpret_cast<uint4*>(wb + AK_OFF + r * QK_STRIDE_B + c * 16) =
            *reinterpret_cast<const uint4*>(qsrc + D_);
        uint4 vv = *reinterpret_cast<const uint4*>(qsrc + 2 * D_);
        const __half* vh = reinterpret_cast<const __half*>(&vv);
#pragma unroll
        for (int j = 0; j < 8; ++j)
            *reinterpret_cast<__half*>(wb + AVT_OFF + (c * 8 + j) * VT_STRIDE_B + r * 2) = vh[j];
    }
    __syncthreads();

    const int a_kh  = lane >> 4;
    const int b_row = (lane & 7) + ((lane >> 4) << 3);
    const int b_kh  = (lane >> 3) & 1;
    const int col0  = (lane & 3) * 2;

    float S[2][4][4];
#pragma unroll
    for (int mi = 0; mi < 2; mi++)
#pragma unroll
        for (int ni = 0; ni < 4; ni++)
#pragma unroll
            for (int e = 0; e < 4; e++) S[mi][ni][e] = 0.f;

#pragma unroll
    for (int s = 0; s < 4; ++s) {
        uint32_t bfr[2][4];
#pragma unroll
        for (int nj = 0; nj < 2; nj++)
            ldsm4(bfr[nj], wbase + AK_OFF +
                  (b_row + nj * 16) * QK_STRIDE_B + (s * 2 + b_kh) * 16);
        uint32_t afr[2][4];
#pragma unroll
        for (int mi = 0; mi < 2; mi++)
            ldsm4(afr[mi], wbase + AQ_OFF +
                  ((lane & 15) + mi * 16) * QK_STRIDE_B + (s * 2 + a_kh) * 16);
#pragma unroll
        for (int mi = 0; mi < 2; mi++)
#pragma unroll
            for (int ni = 0; ni < 4; ni++)
                mma16816(S[mi][ni], afr[mi],
                         bfr[ni >> 1][(ni & 1) * 2], bfr[ni >> 1][(ni & 1) * 2 + 1]);
    }

    float uv[4][2];
#pragma unroll
    for (int ni = 0; ni < 4; ni++) {
        uv[ni][0] = us[8 * ni + col0];
        uv[ni][1] = us[8 * ni + col0 + 1];
    }
    float mA[2] = {-1e30f, -1e30f}, mB[2] = {-1e30f, -1e30f};
#pragma unroll
    for (int mi = 0; mi < 2; mi++)
#pragma unroll
        for (int ni = 0; ni < 4; ni++) {
            S[mi][ni][0] = S[mi][ni][0] * 0.125f - uv[ni][0];
            S[mi][ni][1] = S[mi][ni][1] * 0.125f - uv[ni][1];
            S[mi][ni][2] = S[mi][ni][2] * 0.125f - uv[ni][0];
            S[mi][ni][3] = S[mi][ni][3] * 0.125f - uv[ni][1];
            mA[mi] = fmaxf(mA[mi], fmaxf(S[mi][ni][0], S[mi][ni][1]));
            mB[mi] = fmaxf(mB[mi], fmaxf(S[mi][ni][2], S[mi][ni][3]));
        }
#pragma unroll
    for (int off = 1; off <= 2; off <<= 1) {
#pragma unroll
        for (int mi = 0; mi < 2; mi++) {
            mA[mi] = fmaxf(mA[mi], __shfl_xor_sync(0xffffffffu, mA[mi], off));
            mB[mi] = fmaxf(mB[mi], __shfl_xor_sync(0xffffffffu, mB[mi], off));
        }
    }
    float sA[2] = {0.f, 0.f}, sB[2] = {0.f, 0.f};
#pragma unroll
    for (int mi = 0; mi < 2; mi++)
#pragma unroll
        for (int ni = 0; ni < 4; ni++) {
            S[mi][ni][0] = __expf(S[mi][ni][0] - mA[mi]);
            S[mi][ni][1] = __expf(S[mi][ni][1] - mA[mi]);
            S[mi][ni][2] = __expf(S[mi][ni][2] - mB[mi]);
            S[mi][ni][3] = __expf(S[mi][ni][3] - mB[mi]);
            sA[mi] += S[mi][ni][0] + S[mi][ni][1];
            sB[mi] += S[mi][ni][2] + S[mi][ni][3];
        }
#pragma unroll
    for (int off = 1; off <= 2; off <<= 1) {
#pragma unroll
        for (int mi = 0; mi < 2; mi++) {
            sA[mi] += __shfl_xor_sync(0xffffffffu, sA[mi], off);
            sB[mi] += __shfl_xor_sync(0xffffffffu, sB[mi], off);
        }
    }
    uint32_t p01[2][4], p23[2][4];
#pragma unroll
    for (int mi = 0; mi < 2; mi++) {
        float iA = 1.f / sA[mi], iB = 1.f / sB[mi];
#pragma unroll
        for (int ni = 0; ni < 4; ni++) {
            p01[mi][ni] = packh2(S[mi][ni][0] * iA, S[mi][ni][1] * iA);
            p23[mi][ni] = packh2(S[mi][ni][2] * iB, S[mi][ni][3] * iB);
        }
    }

    float o[2][8][4];
#pragma unroll
    for (int mi = 0; mi < 2; mi++)
#pragma unroll
        for (int ni = 0; ni < 8; ni++)
#pragma unroll
            for (int e = 0; e < 4; e++) o[mi][ni][e] = 0.f;

#pragma unroll
    for (int s = 0; s < 2; ++s) {
        uint32_t bfr[4][4];
#pragma unroll
        for (int nj = 0; nj < 4; nj++)
            ldsm4(bfr[nj], wbase + AVT_OFF +
                  (b_row + nj * 16) * VT_STRIDE_B + (s * 2 + b_kh) * 16);
#pragma unroll
        for (int mi = 0; mi < 2; mi++) {
            uint32_t a[4] = {p01[mi][2 * s], p23[mi][2 * s],
                             p01[mi][2 * s + 1], p23[mi][2 * s + 1]};
#pragma unroll
            for (int ni = 0; ni < 8; ni++)
                mma16816(o[mi][ni], a,
                         bfr[ni >> 1][(ni & 1) * 2], bfr[ni >> 1][(ni & 1) * 2 + 1]);
        }
    }

    // smem-stage O (reuse AQ area; warp-private), then coalesced row stores
    __syncwarp();
    __half* ost = reinterpret_cast<__half*>(wb + AQ_OFF);   // [32][72h]
#pragma unroll
    for (int mi = 0; mi < 2; mi++) {
        int rA = (lane >> 2) + 16 * mi;
#pragma unroll
        for (int ni = 0; ni < 8; ni++) {
            int d = 8 * ni + col0;
            store2(ost + (size_t)rA * 72 + d,       o[mi][ni][0], o[mi][ni][1]);
            store2(ost + (size_t)(rA + 8) * 72 + d, o[mi][ni][2], o[mi][ni][3]);
        }
    }
    __syncwarp();
    __half* ob = O + (size_t)bs * D_ + head * HD_;    // aout [t][bs][d]
    const size_t ostride = (size_t)BS_ * D_;
#pragma unroll
    for (int r = 0; r < 32; ++r) {
        uint32_t v = *reinterpret_cast<uint32_t*>(ost + (size_t)r * 72 + lane * 2);
        *reinterpret_cast<uint32_t*>(ob + (size_t)r * ostride + lane * 2) = v;
    }
}

// ---------------------------------------------------------------------------
extern "C" void kernel_launch(void* const* d_in, const int* in_sizes, int n_in,
                              void* d_out, int out_size) {
    const float* h   = (const float*)d_in[0];
    const float* u   = (const float*)d_in[1];
    const float* lam = (const float*)d_in[2];
    const float* Wq  = (const float*)d_in[3];
    const float* bq  = (const float*)d_in[4];
    const float* Wk  = (const float*)d_in[5];
    const float* bk  = (const float*)d_in[6];
    const float* Wv  = (const float*)d_in[7];
    const float* bv  = (const float*)d_in[8];
    const float* Wo  = (const float*)d_in[9];
    const float* bo  = (const float*)d_in[10];
    float* out = (float*)d_out;

    __half *hh, *aout, *wqkv, *wo, *QKVh;
    float *bqkv, *upen;
    cudaGetSymbolAddress((void**)&hh,   g_hh);
    cudaGetSymbolAddress((void**)&aout, g_aout);
    cudaGetSymbolAddress((void**)&wqkv, g_wqkv);
    cudaGetSymbolAddress((void**)&wo,   g_wo);
    cudaGetSymbolAddress((void**)&bqkv, g_bqkv);
    cudaGetSymbolAddress((void**)&QKVh, g_QKV);
    cudaGetSymbolAddress((void**)&upen, g_upen);

    cudaFuncSetAttribute(gemm_qkv, cudaFuncAttributeMaxDynamicSharedMemorySize,
                         3 * STG_BYTES);
    cudaFuncSetAttribute(gemm_oproj, cudaFuncAttributeMaxDynamicSharedMemorySize,
                         3 * STG_BYTES);
    cudaFuncSetAttribute(attn_mma, cudaFuncAttributeMaxDynamicSharedMemorySize,
                         ATTN_SMEM);

    dim3 tgrid(P_ / 32, D_ / 64, 128), tblk(32, 32);
    transpose_in_h<<<tgrid, tblk>>>(h, hh);
    upen_kernel<<<128, 256>>>(u, lam, upen);
    dim3 wgrid((D_ * D_) / 1024, 4);
    wconv4<<<wgrid, 256>>>(Wq, Wk, Wv, Wo, wqkv, wo, bq, bk, bv, bqkv);

    // fused QKV projection: C[M, 2304] fp16, rows [bs][t]
    dim3 qgrid(NQKV / BN, M_ / BM);        // (18, 256)
    gemm_qkv<<<qgrid, 128, 3 * STG_BYTES>>>(hh, wqkv, bqkv, QKVh);

    dim3 agrid(BS_, 3);
    attn_mma<<<agrid, 128, ATTN_SMEM>>>(QKVh, upen, aout);

    // O projection with fused transpose -> writes final out directly
    dim3 ogrid(D_ / BN, M_ / BM);          // (6, 256)
    gemm_oproj<<<ogrid, 128, 3 * STG_BYTES>>>(aout, wo, bo, out);
}

// round 17
// speedup vs baseline: 1.0154x; 1.0154x over previous
#include <cuda_runtime.h>
#include <cuda_fp16.h>
#include <cstdint>

// Problem constants
#define B_   4
#define T_   32
#define D_   768
#define P_   256
#define BS_  1024
#define M_   32768
#define NH_  12
#define HD_  64
#define NQKV 2304          // fused Q|K|V output width

// hh / QKV rows: m = bs*T + t   (attention-friendly)
// aout rows:     m = t*BS + bs  (oproj fused-transpose-friendly)

// GEMM tiling: 128x128, BK=64, 4 warps (2m x 2n), warp tile 64x64,
// 2-stage cp.async pipeline, 3 CTAs/SM.
#define BM   128
#define BN   128
#define BK   64
#define NKT  (D_ / BK)     // 12
#define STG_BYTES 32768    // A 16K + B 16K
#define B_OFFS 16384
#define QKV_SMEM  (2 * STG_BYTES)          // 65536
#define OPROJ_SMEM 66048                   // max(2 stages, 128*129*4 epilogue)

#define SW128(b) ((b) ^ (((b) >> 3) & 0x70))

// Attention smem layout (per warp): Q 32x72h, K 32x72h, Vt 64x40h
#define QK_STRIDE_B 144
#define VT_STRIDE_B 80
#define AQ_OFF 0
#define AK_OFF 4608
#define AVT_OFF 9216
#define AWARP_BYTES 14336
#define AUPEN_OFF (4 * AWARP_BYTES)
#define ATTN_SMEM (AUPEN_OFF + 128)

// ---------------- scratch (device globals; no cudaMalloc allowed) ----------
__device__ __half g_hh  [(size_t)M_ * D_];       // h_seq fp16, [bs][t][d]
__device__ __half g_aout[(size_t)M_ * D_];       // attention out fp16, [t][bs][d]
__device__ __half g_wqkv[(size_t)NQKV * D_];     // fused Wq|Wk|Wv fp16
__device__ __half g_wo  [(size_t)D_ * D_];
__device__ float  g_bqkv[NQKV];
__device__ __half g_QKV [(size_t)M_ * NQKV];     // fused Q|K|V fp16, [bs][t]
__device__ float  g_upen[M_];                    // [bs][t]

// ---------------- PTX helpers (base-PTX, sm_80-era) ------------------------
__device__ __forceinline__ uint32_t smem_u32(const void* p) {
    uint32_t a;
    asm("{ .reg .u64 t; cvta.to.shared.u64 t, %1; cvt.u32.u64 %0, t; }"
        : "=r"(a) : "l"(p));
    return a;
}

__device__ __forceinline__ void cp16(uint32_t dst, const void* src) {
    asm volatile("cp.async.cg.shared.global [%0], [%1], 16;" :: "r"(dst), "l"(src));
}
#define CP_COMMIT() asm volatile("cp.async.commit_group;" ::: "memory")
#define CP_WAIT(n)  asm volatile("cp.async.wait_group %0;" :: "n"(n) : "memory")

__device__ __forceinline__ void ldsm4(uint32_t (&r)[4], uint32_t addr) {
    asm volatile("ldmatrix.sync.aligned.m8n8.x4.shared.b16 {%0,%1,%2,%3}, [%4];"
                 : "=r"(r[0]), "=r"(r[1]), "=r"(r[2]), "=r"(r[3]) : "r"(addr));
}

__device__ __forceinline__ void mma16816(float (&d)[4], const uint32_t (&a)[4],
                                         uint32_t b0, uint32_t b1) {
    asm volatile(
        "mma.sync.aligned.m16n8k16.row.col.f32.f16.f16.f32 "
        "{%0,%1,%2,%3}, {%4,%5,%6,%7}, {%8,%9}, {%0,%1,%2,%3};"
        : "+f"(d[0]), "+f"(d[1]), "+f"(d[2]), "+f"(d[3])
        : "r"(a[0]), "r"(a[1]), "r"(a[2]), "r"(a[3]), "r"(b0), "r"(b1));
}

__device__ __forceinline__ uint32_t packh2(float x, float y) {
    __half2 h = __floats2half2_rn(x, y);
    return *reinterpret_cast<uint32_t*>(&h);
}

__device__ __forceinline__ void store2(float* p, float x, float y) {
    *reinterpret_cast<float2*>(p) = make_float2(x, y);
}
__device__ __forceinline__ void store2(__half* p, float x, float y) {
    *reinterpret_cast<__half2*>(p) = __floats2half2_rn(x, y);
}

// ---------------------------------------------------------------------------
// transpose to [bs][t][d] + fp16 convert; 64d x 32p tiles, __half2 stores
// ---------------------------------------------------------------------------
__global__ __launch_bounds__(1024) void transpose_in_h(const float* __restrict__ src,
                                                       __half* __restrict__ dst) {
    __shared__ float tile[64][33];
    int bt = blockIdx.z, b = bt >> 5, t = bt & 31;
    int dblk = blockIdx.y * 64, pblk = blockIdx.x * 32;
    int tx = threadIdx.x, ty = threadIdx.y;

    const float* sp = src + ((size_t)bt * D_ + dblk + ty) * P_ + pblk + tx;
    tile[ty][tx]      = sp[0];
    tile[ty + 32][tx] = sp[(size_t)32 * P_];
    __syncthreads();
    int d2 = 2 * tx;
    int p2 = pblk + ty;
    __half2 v = __floats2half2_rn(tile[d2][ty], tile[d2 + 1][ty]);
    *reinterpret_cast<__half2*>(
        dst + ((size_t)(b * P_ + p2) * T_ + t) * D_ + dblk + d2) = v;
}

// ---------------------------------------------------------------------------
// weight convert (all 4) + bias pack fold
// ---------------------------------------------------------------------------
__global__ __launch_bounds__(256) void wconv4(const float* __restrict__ Wq,
                                              const float* __restrict__ Wk,
                                              const float* __restrict__ Wv,
                                              const float* __restrict__ Wo,
                                              __half* __restrict__ wqkv,
                                              __half* __restrict__ wo,
                                              const float* __restrict__ bq,
                                              const float* __restrict__ bk,
                                              const float* __restrict__ bv,
                                              float* __restrict__ bqkv) {
    int idx = blockIdx.x * 256 + threadIdx.x;
    int w = blockIdx.y;
    const float* src = (w == 0) ? Wq : (w == 1) ? Wk : (w == 2) ? Wv : Wo;
    __half* dst = (w == 3) ? wo : wqkv + (size_t)w * D_ * D_;
    float4 v = *reinterpret_cast<const float4*>(src + idx * 4);
    __half2 h0 = __floats2half2_rn(v.x, v.y);
    __half2 h1 = __floats2half2_rn(v.z, v.w);
    uint2 o = make_uint2(*reinterpret_cast<uint32_t*>(&h0),
                         *reinterpret_cast<uint32_t*>(&h1));
    *reinterpret_cast<uint2*>(dst + idx * 4) = o;

    if (w == 3 && idx < NQKV) {
        float bv_ = (idx < D_) ? bq[idx]
                  : (idx < 2 * D_) ? bk[idx - D_] : bv[idx - 2 * D_];
        bqkv[idx] = bv_;
    }
}

// ---------------------------------------------------------------------------
// u_pen   [bs][t]
// ---------------------------------------------------------------------------
__global__ __launch_bounds__(256) void upen_kernel(const float* __restrict__ u,
                                                   const float* __restrict__ lam,
                                                   float* __restrict__ upen) {
    int bt = blockIdx.x, b = bt >> 5, t = bt & 31;
    int p = threadIdx.x;
    const float* up = u + (size_t)bt * D_ * P_ + p;
    float acc = 0.f;
#pragma unroll 8
    for (int d = 0; d < D_; d++) acc += up[(size_t)d * P_];
    upen[(b * P_ + p) * T_ + t] = lam[(size_t)bt * P_ + p] * acc * (1.0f / (float)D_);
}

// ---------------------------------------------------------------------------
// GEMM core: 128x128x768, 4 warps x (64x64), 2-stage pipeline.
// ---------------------------------------------------------------------------
struct GemmAcc { float a[4][8][4]; };

template <typename EpiF>
__device__ __forceinline__ void gemm_core(const __half* __restrict__ A,
                                          const __half* __restrict__ Wt,
                                          char* dyn, int mblk, int nblk,
                                          EpiF epi) {
    const uint32_t dynb = smem_u32(dyn);
    const int tid  = threadIdx.x;
    const int wid  = tid >> 5;
    const int lane = tid & 31;

    const int warp_m = (wid >> 1) * 64;   // 0,64
    const int warp_n = (wid & 1) * 64;    // 0,64

    const __half* Ab = A  + (size_t)mblk * D_;
    const __half* Bb = Wt + (size_t)nblk * D_;

    // 2048 chunks / 128 threads = 16 per thread
    auto load_tile = [&](int stage, int kt) {
        uint32_t sb = dynb + stage * STG_BYTES;
        const __half* Ak = Ab + kt * BK;
        const __half* Bk = Bb + kt * BK;
#pragma unroll
        for (int i = 0; i < 16; ++i) {
            int c = tid + 128 * i;
            if (c < 1024) {
                int r = c >> 3, kc = c & 7;
                cp16(sb + SW128(r * 128 + kc * 16),
                     Ak + (size_t)r * D_ + kc * 8);
            } else {
                int c2 = c - 1024;
                int r = c2 >> 3, kc = c2 & 7;
                cp16(sb + B_OFFS + SW128(r * 128 + kc * 16),
                     Bk + (size_t)r * D_ + kc * 8);
            }
        }
        CP_COMMIT();
    };

    const int a_row = warp_m + (lane & 15);
    const int a_kh  = lane >> 4;
    const int b_row = warp_n + (lane & 7) + ((lane >> 4) << 3);
    const int b_kh  = (lane >> 3) & 1;

    GemmAcc acc;
#pragma unroll
    for (int mi = 0; mi < 4; mi++)
#pragma unroll
        for (int ni = 0; ni < 8; ni++)
#pragma unroll
            for (int e = 0; e < 4; e++) acc.a[mi][ni][e] = 0.f;

    load_tile(0, 0);
    load_tile(1, 1);

    for (int kt = 0; kt < NKT; ++kt) {
        const int cur = kt & 1;
        if (kt < NKT - 1) CP_WAIT(1); else CP_WAIT(0);
        __syncthreads();

        const uint32_t sb = dynb + cur * STG_BYTES;
#pragma unroll
        for (int s = 0; s < 4; ++s) {
            uint32_t bfr[4][4];
#pragma unroll
            for (int nj = 0; nj < 4; nj++)
                ldsm4(bfr[nj], sb + B_OFFS +
                      SW128((b_row + nj * 16) * 128 + (s * 2 + b_kh) * 16));
            uint32_t afr[4][4];
#pragma unroll
            for (int mi = 0; mi < 4; mi++)
                ldsm4(afr[mi], sb +
                      SW128((a_row + mi * 16) * 128 + (s * 2 + a_kh) * 16));
#pragma unroll
            for (int mi = 0; mi < 4; mi++) {
#pragma unroll
                for (int ni = 0; ni < 8; ni++) {
                    uint32_t b0 = bfr[ni >> 1][(ni & 1) * 2 + 0];
                    uint32_t b1 = bfr[ni >> 1][(ni & 1) * 2 + 1];
                    mma16816(acc.a[mi][ni], afr[mi], b0, b1);
                }
            }
        }

        if (kt + 2 < NKT) {
            __syncthreads();               // all warps done reading buf cur
            load_tile(cur, kt + 2);
        }
    }
    epi(acc, warp_m, warp_n, lane);
}

// ---------------------------------------------------------------------------
// HMMA GEMM (QKV): C fp16 stride NQKV, smem-staged coalesced epilogue
// ---------------------------------------------------------------------------
__global__ __launch_bounds__(128, 3) void gemm_qkv(const __half* __restrict__ A,
                                                   const __half* __restrict__ Wt,
                                                   const float* __restrict__ bias,
                                                   __half* __restrict__ C) {
    extern __shared__ __align__(128) char dyn[];
    const int mblk = blockIdx.y * BM;
    const int nblk = blockIdx.x * BN;
    const int tid  = threadIdx.x;
    const int wid  = tid >> 5;

    gemm_core(A, Wt, dyn, mblk, nblk,
        [&](GemmAcc& acc, int warp_m, int warp_n, int lane) {
            const int rloc0 = warp_m + (lane >> 2);
            const int cloc0 = warp_n + (lane & 3) * 2;
            float2 bb[8];
#pragma unroll
            for (int ni = 0; ni < 8; ni++) {
                int n = nblk + cloc0 + ni * 8;
                bb[ni].x = __ldg(&bias[n]);
                bb[ni].y = __ldg(&bias[n + 1]);
            }
            __syncthreads();
            __half* cst = reinterpret_cast<__half*>(dyn);
#pragma unroll
            for (int mi = 0; mi < 4; mi++) {
                int r0 = rloc0 + mi * 16;
#pragma unroll
                for (int ni = 0; ni < 8; ni++) {
                    int n = cloc0 + ni * 8;
                    store2(cst + (size_t)r0 * 136 + n,
                           acc.a[mi][ni][0] + bb[ni].x, acc.a[mi][ni][1] + bb[ni].y);
                    store2(cst + (size_t)(r0 + 8) * 136 + n,
                           acc.a[mi][ni][2] + bb[ni].x, acc.a[mi][ni][3] + bb[ni].y);
                }
            }
            __syncthreads();
#pragma unroll
            for (int i = 0; i < 32; ++i) {
                int r = wid * 32 + i;
                uint2 v = *reinterpret_cast<uint2*>(cst + (size_t)r * 136 + lane * 4);
                *reinterpret_cast<uint2*>(C + (size_t)(mblk + r) * NQKV + nblk + lane * 4) = v;
            }
        });
}

// ---------------------------------------------------------------------------
// HMMA GEMM (O proj) with FUSED TRANSPOSE epilogue:
// A = aout [t][bs][d]; writes final out (B,T,D,P) fp32 directly.
// ---------------------------------------------------------------------------
__global__ __launch_bounds__(128, 3) void gemm_oproj(const __half* __restrict__ A,
                                                     const __half* __restrict__ Wt,
                                                     const float* __restrict__ bias,
                                                     float* __restrict__ out) {
    extern __shared__ __align__(128) char dyn[];
    const int mblk = blockIdx.y * BM;
    const int nblk = blockIdx.x * BN;
    const int tid  = threadIdx.x;

    gemm_core(A, Wt, dyn, mblk, nblk,
        [&](GemmAcc& acc, int warp_m, int warp_n, int lane) {
            float* stage = reinterpret_cast<float*>(dyn);
            const int rloc0 = warp_m + (lane >> 2);
            const int nloc0 = warp_n + (lane & 3) * 2;
            float2 bb[8];
#pragma unroll
            for (int ni = 0; ni < 8; ni++) {
                int n = nblk + nloc0 + ni * 8;
                bb[ni].x = __ldg(&bias[n]);
                bb[ni].y = __ldg(&bias[n + 1]);
            }
            __syncthreads();
#pragma unroll
            for (int mi = 0; mi < 4; mi++) {
                int r0 = rloc0 + mi * 16;
#pragma unroll
                for (int ni = 0; ni < 8; ni++) {
                    int n = nloc0 + ni * 8;
                    stage[(size_t)r0 * 129 + n]           = acc.a[mi][ni][0] + bb[ni].x;
                    stage[(size_t)r0 * 129 + n + 1]       = acc.a[mi][ni][1] + bb[ni].y;
                    stage[(size_t)(r0 + 8) * 129 + n]     = acc.a[mi][ni][2] + bb[ni].x;
                    stage[(size_t)(r0 + 8) * 129 + n + 1] = acc.a[mi][ni][3] + bb[ni].y;
                }
            }
            __syncthreads();

            const int t  = mblk >> 10;
            const int b  = (mblk & 1023) >> 8;
            const int p0 = mblk & 255;
            float* obase = out + ((size_t)(b * T_ + t) * D_ + nblk) * P_ + p0;
#pragma unroll
            for (int i = 0; i < 32; ++i) {
                int c = tid + 128 * i;
                int dn = c >> 5, f4 = c & 31;
                float4 v;
                v.x = stage[(size_t)(f4 * 4 + 0) * 129 + dn];
                v.y = stage[(size_t)(f4 * 4 + 1) * 129 + dn];
                v.z = stage[(size_t)(f4 * 4 + 2) * 129 + dn];
                v.w = stage[(size_t)(f4 * 4 + 3) * 129 + dn];
                *reinterpret_cast<float4*>(obase + (size_t)dn * P_ + f4 * 4) = v;
            }
        });
}

// ---------------------------------------------------------------------------
// HMMA attention: 1 warp per (bs, head). QKV [bs][t] contiguous loads;
// writes aout [t][bs] via smem-staged coalesced row stores.
// ---------------------------------------------------------------------------
__global__ __launch_bounds__(128) void attn_mma(const __half* __restrict__ QKV,
                                                const float* __restrict__ upen,
                                                __half* __restrict__ O) {
    extern __shared__ __align__(128) char asm_[];
    const int bs   = blockIdx.x;
    const int wid  = threadIdx.x >> 5;
    const int lane = threadIdx.x & 31;
    const int head = blockIdx.y * 4 + wid;

    char* wb = asm_ + wid * AWARP_BYTES;
    const uint32_t wbase = smem_u32(asm_) + wid * AWARP_BYTES;
    float* us = reinterpret_cast<float*>(asm_ + AUPEN_OFF);

    if (threadIdx.x < 32) us[threadIdx.x] = upen[bs * T_ + threadIdx.x];

    const __half* hb = QKV + (size_t)(bs * T_) * NQKV + head * HD_;
#pragma unroll
    for (int i = 0; i < 8; ++i) {
        int id = lane + 32 * i;
        int r = id >> 3, c = id & 7;
        const __half* qsrc = hb + (size_t)r * NQKV + c * 8;
        *reinterpret_cast<uint4*>(wb + AQ_OFF + r * QK_STRIDE_B + c * 16) =
            *reinterpret_cast<const uint4*>(qsrc);
        *reinterpret_cast<uint4*>(wb + AK_OFF + r * QK_STRIDE_B + c * 16) =
            *reinterpret_cast<const uint4*>(qsrc + D_);
        uint4 vv = *reinterpret_cast<const uint4*>(qsrc + 2 * D_);
        const __half* vh = reinterpret_cast<const __half*>(&vv);
#pragma unroll
        for (int j = 0; j < 8; ++j)
            *reinterpret_cast<__half*>(wb + AVT_OFF + (c * 8 + j) * VT_STRIDE_B + r * 2) = vh[j];
    }
    __syncthreads();

    const int a_kh  = lane >> 4;
    const int b_row = (lane & 7) + ((lane >> 4) << 3);
    const int b_kh  = (lane >> 3) & 1;
    const int col0  = (lane & 3) * 2;

    float S[2][4][4];
#pragma unroll
    for (int mi = 0; mi < 2; mi++)
#pragma unroll
        for (int ni = 0; ni < 4; ni++)
#pragma unroll
            for (int e = 0; e < 4; e++) S[mi][ni][e] = 0.f;

#pragma unroll
    for (int s = 0; s < 4; ++s) {
        uint32_t bfr[2][4];
#pragma unroll
        for (int nj = 0; nj < 2; nj++)
            ldsm4(bfr[nj], wbase + AK_OFF +
                  (b_row + nj * 16) * QK_STRIDE_B + (s * 2 + b_kh) * 16);
        uint32_t afr[2][4];
#pragma unroll
        for (int mi = 0; mi < 2; mi++)
            ldsm4(afr[mi], wbase + AQ_OFF +
                  ((lane & 15) + mi * 16) * QK_STRIDE_B + (s * 2 + a_kh) * 16);
#pragma unroll
        for (int mi = 0; mi < 2; mi++)
#pragma unroll
            for (int ni = 0; ni < 4; ni++)
                mma16816(S[mi][ni], afr[mi],
                         bfr[ni >> 1][(ni & 1) * 2], bfr[ni >> 1][(ni & 1) * 2 + 1]);
    }

    float uv[4][2];
#pragma unroll
    for (int ni = 0; ni < 4; ni++) {
        uv[ni][0] = us[8 * ni + col0];
        uv[ni][1] = us[8 * ni + col0 + 1];
    }
    float mA[2] = {-1e30f, -1e30f}, mB[2] = {-1e30f, -1e30f};
#pragma unroll
    for (int mi = 0; mi < 2; mi++)
#pragma unroll
        for (int ni = 0; ni < 4; ni++) {
            S[mi][ni][0] = S[mi][ni][0] * 0.125f - uv[ni][0];
            S[mi][ni][1] = S[mi][ni][1] * 0.125f - uv[ni][1];
            S[mi][ni][2] = S[mi][ni][2] * 0.125f - uv[ni][0];
            S[mi][ni][3] = S[mi][ni][3] * 0.125f - uv[ni][1];
            mA[mi] = fmaxf(mA[mi], fmaxf(S[mi][ni][0], S[mi][ni][1]));
            mB[mi] = fmaxf(mB[mi], fmaxf(S[mi][ni][2], S[mi][ni][3]));
        }
#pragma unroll
    for (int off = 1; off <= 2; off <<= 1) {
#pragma unroll
        for (int mi = 0; mi < 2; mi++) {
            mA[mi] = fmaxf(mA[mi], __shfl_xor_sync(0xffffffffu, mA[mi], off));
            mB[mi] = fmaxf(mB[mi], __shfl_xor_sync(0xffffffffu, mB[mi], off));
        }
    }
    float sA[2] = {0.f, 0.f}, sB[2] = {0.f, 0.f};
#pragma unroll
    for (int mi = 0; mi < 2; mi++)
#pragma unroll
        for (int ni = 0; ni < 4; ni++) {
            S[mi][ni][0] = __expf(S[mi][ni][0] - mA[mi]);
            S[mi][ni][1] = __expf(S[mi][ni][1] - mA[mi]);
            S[mi][ni][2] = __expf(S[mi][ni][2] - mB[mi]);
            S[mi][ni][3] = __expf(S[mi][ni][3] - mB[mi]);
            sA[mi] += S[mi][ni][0] + S[mi][ni][1];
            sB[mi] += S[mi][ni][2] + S[mi][ni][3];
        }
#pragma unroll
    for (int off = 1; off <= 2; off <<= 1) {
#pragma unroll
        for (int mi = 0; mi < 2; mi++) {
            sA[mi] += __shfl_xor_sync(0xffffffffu, sA[mi], off);
            sB[mi] += __shfl_xor_sync(0xffffffffu, sB[mi], off);
        }
    }
    uint32_t p01[2][4], p23[2][4];
#pragma unroll
    for (int mi = 0; mi < 2; mi++) {
        float iA = 1.f / sA[mi], iB = 1.f / sB[mi];
#pragma unroll
        for (int ni = 0; ni < 4; ni++) {
            p01[mi][ni] = packh2(S[mi][ni][0] * iA, S[mi][ni][1] * iA);
            p23[mi][ni] = packh2(S[mi][ni][2] * iB, S[mi][ni][3] * iB);
        }
    }

    float o[2][8][4];
#pragma unroll
    for (int mi = 0; mi < 2; mi++)
#pragma unroll
        for (int ni = 0; ni < 8; ni++)
#pragma unroll
            for (int e = 0; e < 4; e++) o[mi][ni][e] = 0.f;

#pragma unroll
    for (int s = 0; s < 2; ++s) {
        uint32_t bfr[4][4];
#pragma unroll
        for (int nj = 0; nj < 4; nj++)
            ldsm4(bfr[nj], wbase + AVT_OFF +
                  (b_row + nj * 16) * VT_STRIDE_B + (s * 2 + b_kh) * 16);
#pragma unroll
        for (int mi = 0; mi < 2; mi++) {
            uint32_t a[4] = {p01[mi][2 * s], p23[mi][2 * s],
                             p01[mi][2 * s + 1], p23[mi][2 * s + 1]};
#pragma unroll
            for (int ni = 0; ni < 8; ni++)
                mma16816(o[mi][ni], a,
                         bfr[ni >> 1][(ni & 1) * 2], bfr[ni >> 1][(ni & 1) * 2 + 1]);
        }
    }

    // smem-stage O (reuse AQ area; warp-private), then coalesced row stores
    __syncwarp();
    __half* ost = reinterpret_cast<__half*>(wb + AQ_OFF);   // [32][72h]
#pragma unroll
    for (int mi = 0; mi < 2; mi++) {
        int rA = (lane >> 2) + 16 * mi;
#pragma unroll
        for (int ni = 0; ni < 8; ni++) {
            int d = 8 * ni + col0;
            store2(ost + (size_t)rA * 72 + d,       o[mi][ni][0], o[mi][ni][1]);
            store2(ost + (size_t)(rA + 8) * 72 + d, o[mi][ni][2], o[mi][ni][3]);
        }
    }
    __syncwarp();
    __half* ob = O + (size_t)bs * D_ + head * HD_;    // aout [t][bs][d]
    const size_t ostride = (size_t)BS_ * D_;
#pragma unroll
    for (int r = 0; r < 32; ++r) {
        uint32_t v = *reinterpret_cast<uint32_t*>(ost + (size_t)r * 72 + lane * 2);
        *reinterpret_cast<uint32_t*>(ob + (size_t)r * ostride + lane * 2) = v;
    }
}

// ---------------------------------------------------------------------------
extern "C" void kernel_launch(void* const* d_in, const int* in_sizes, int n_in,
                              void* d_out, int out_size) {
    const float* h   = (const float*)d_in[0];
    const float* u   = (const float*)d_in[1];
    const float* lam = (const float*)d_in[2];
    const float* Wq  = (const float*)d_in[3];
    const float* bq  = (const float*)d_in[4];
    const float* Wk  = (const float*)d_in[5];
    const float* bk  = (const float*)d_in[6];
    const float* Wv  = (const float*)d_in[7];
    const float* bv  = (const float*)d_in[8];
    const float* Wo  = (const float*)d_in[9];
    const float* bo  = (const float*)d_in[10];
    float* out = (float*)d_out;

    __half *hh, *aout, *wqkv, *wo, *QKVh;
    float *bqkv, *upen;
    cudaGetSymbolAddress((void**)&hh,   g_hh);
    cudaGetSymbolAddress((void**)&aout, g_aout);
    cudaGetSymbolAddress((void**)&wqkv, g_wqkv);
    cudaGetSymbolAddress((void**)&wo,   g_wo);
    cudaGetSymbolAddress((void**)&bqkv, g_bqkv);
    cudaGetSymbolAddress((void**)&QKVh, g_QKV);
    cudaGetSymbolAddress((void**)&upen, g_upen);

    cudaFuncSetAttribute(gemm_qkv, cudaFuncAttributeMaxDynamicSharedMemorySize,
                         QKV_SMEM);
    cudaFuncSetAttribute(gemm_oproj, cudaFuncAttributeMaxDynamicSharedMemorySize,
                         OPROJ_SMEM);
    cudaFuncSetAttribute(attn_mma, cudaFuncAttributeMaxDynamicSharedMemorySize,
                         ATTN_SMEM);

    dim3 tgrid(P_ / 32, D_ / 64, 128), tblk(32, 32);
    transpose_in_h<<<tgrid, tblk>>>(h, hh);
    upen_kernel<<<128, 256>>>(u, lam, upen);
    dim3 wgrid((D_ * D_) / 1024, 4);
    wconv4<<<wgrid, 256>>>(Wq, Wk, Wv, Wo, wqkv, wo, bq, bk, bv, bqkv);

    // fused QKV projection: C[M, 2304] fp16, rows [bs][t]
    dim3 qgrid(NQKV / BN, M_ / BM);        // (18, 256)
    gemm_qkv<<<qgrid, 128, QKV_SMEM>>>(hh, wqkv, bqkv, QKVh);

    dim3 agrid(BS_, 3);
    attn_mma<<<agrid, 128, ATTN_SMEM>>>(QKVh, upen, aout);

    // O projection with fused transpose -> writes final out directly
    dim3 ogrid(D_ / BN, M_ / BM);          // (6, 256)
    gemm_oproj<<<ogrid, 128, OPROJ_SMEM>>>(aout, wo, bo, out);
}